// round 1
// baseline (speedup 1.0000x reference)
#include <cuda_runtime.h>

#define BN 64
#define RN 2048
#define CN 32
#define ON 32
#define INN 16
#define CO 1024  // CN*ON

#define K1_RT 8
#define K1_NRT 256  // RN / K1_RT
#define RT_RT 64
#define RT_NRT 32   // RN / RT_RT

// Scratch (device globals: allocation-free per harness rules)
__device__ float g_uhat[(size_t)BN * RN * CO];         // 512 MiB
__device__ float g_part0[(size_t)K1_NRT * BN * CO];    // 64 MiB (s0 partials)
__device__ float g_part[(size_t)RT_NRT * BN * CO];     // 8 MiB  (s1/s2 partials)
__device__ float g_blog[(size_t)BN * RN * CN];         // 16 MiB (routing logits)
__device__ float g_v[BN * CO];                         // v buffer

__device__ __forceinline__ float dot4(float4 a, float4 b) {
    return a.x * b.x + a.y * b.y + a.z * b.z + a.w * b.w;
}

// -------- K1: u_hat[b,r,c,o] = sum_i W[r,c,o,i] * x[b,r,i]; fused s0 partials --------
// grid (4, 256): blockIdx.x = b-block (16 b), blockIdx.y = r-tile (8 r)
// 256 threads = 8 b-pair groups x 32 co-lanes; thread: 2 b x 32 co (4 consecutive co x 8)
__global__ void __launch_bounds__(256) k1_uhat(const float* __restrict__ x,
                                               const float* __restrict__ W) {
    const int bb = blockIdx.x;
    const int rt = blockIdx.y;
    const int t  = threadIdx.x;
    const int bg = t >> 5;
    const int cl = t & 31;
    const int b0 = bb * 16 + bg * 2;
    const int b1 = b0 + 1;

    float s0a[8][4], s0b[8][4];
    #pragma unroll
    for (int k = 0; k < 8; k++)
        #pragma unroll
        for (int cc = 0; cc < 4; cc++) { s0a[k][cc] = 0.f; s0b[k][cc] = 0.f; }

    for (int rj = 0; rj < K1_RT; rj++) {
        const int r = rt * K1_RT + rj;
        const float4* xp0 = (const float4*)(x + ((size_t)b0 * RN + r) * INN);
        const float4* xp1 = (const float4*)(x + ((size_t)b1 * RN + r) * INN);
        float4 xa[4], xb[4];
        #pragma unroll
        for (int q = 0; q < 4; q++) { xa[q] = xp0[q]; xb[q] = xp1[q]; }

        const float4* wp = (const float4*)(W + (size_t)r * CO * INN);
        float* u0 = g_uhat + ((size_t)b0 * RN + r) * CO;
        float* u1 = g_uhat + ((size_t)b1 * RN + r) * CO;

        #pragma unroll
        for (int k = 0; k < 8; k++) {
            const int cobase = cl * 4 + 128 * k;
            float4 o0, o1;
            #pragma unroll
            for (int cc = 0; cc < 4; cc++) {
                const float4* wr = wp + (size_t)(cobase + cc) * 4;
                float a0 = 0.f, a1 = 0.f;
                #pragma unroll
                for (int q = 0; q < 4; q++) {
                    const float4 w4 = wr[q];
                    a0 += dot4(w4, xa[q]);
                    a1 += dot4(w4, xb[q]);
                }
                (&o0.x)[cc] = a0;
                (&o1.x)[cc] = a1;
                s0a[k][cc] += a0;
                s0b[k][cc] += a1;
            }
            *(float4*)(u0 + cobase) = o0;
            *(float4*)(u1 + cobase) = o1;
        }
    }

    float* p0 = g_part0 + ((size_t)rt * BN + b0) * CO;
    float* p1 = g_part0 + ((size_t)rt * BN + b1) * CO;
    #pragma unroll
    for (int k = 0; k < 8; k++) {
        const int cobase = cl * 4 + 128 * k;
        *(float4*)(p0 + cobase) = make_float4(s0a[k][0], s0a[k][1], s0a[k][2], s0a[k][3]);
        *(float4*)(p1 + cobase) = make_float4(s0b[k][0], s0b[k][1], s0b[k][2], s0b[k][3]);
    }
}

// -------- routing pass: b-update + softmax(c) + weighted s accumulation --------
// grid (64, 32): blockIdx.x = b, blockIdx.y = r-tile (64 r). 8 warps; lane = c (C==32).
__global__ void __launch_bounds__(256) k_route(const int first, const int write_b) {
    const int b  = blockIdx.x;
    const int rt = blockIdx.y;
    const int t  = threadIdx.x;
    const int w  = t >> 5;
    const int l  = t & 31;  // capsule c

    float4 vv[8];
    const float4* vp = (const float4*)(g_v + (size_t)b * CO + l * ON);
    #pragma unroll
    for (int k = 0; k < 8; k++) vv[k] = vp[k];

    float4 acc[8];
    #pragma unroll
    for (int k = 0; k < 8; k++) acc[k] = make_float4(0.f, 0.f, 0.f, 0.f);

    for (int j = 0; j < 8; j++) {
        const int r = rt * RT_RT + w * 8 + j;
        const float4* up = (const float4*)(g_uhat + ((size_t)b * RN + r) * CO + l * ON);
        float4 u[8];
        #pragma unroll
        for (int k = 0; k < 8; k++) u[k] = up[k];

        float d = 0.f;
        #pragma unroll
        for (int k = 0; k < 8; k++) d += dot4(u[k], vv[k]);

        const size_t bi = ((size_t)b * RN + r) * CN + l;
        const float bn = d + (first ? 0.f : g_blog[bi]);
        if (write_b) g_blog[bi] = bn;

        float m = bn;
        #pragma unroll
        for (int s = 16; s; s >>= 1) m = fmaxf(m, __shfl_xor_sync(0xffffffffu, m, s));
        const float e = __expf(bn - m);
        float sum = e;
        #pragma unroll
        for (int s = 16; s; s >>= 1) sum += __shfl_xor_sync(0xffffffffu, sum, s);
        const float coef = e / sum;

        #pragma unroll
        for (int k = 0; k < 8; k++) {
            acc[k].x += coef * u[k].x;
            acc[k].y += coef * u[k].y;
            acc[k].z += coef * u[k].z;
            acc[k].w += coef * u[k].w;
        }
    }

    __shared__ float sred[8 * CO];
    #pragma unroll
    for (int k = 0; k < 8; k++)
        *(float4*)(sred + w * CO + l * ON + 4 * k) = acc[k];
    __syncthreads();

    #pragma unroll
    for (int m4 = 0; m4 < 4; m4++) {
        const int co = t + 256 * m4;
        float s = 0.f;
        #pragma unroll
        for (int ww = 0; ww < 8; ww++) s += sred[ww * CO + co];
        g_part[((size_t)rt * BN + b) * CO + co] = s;
    }
}

// -------- squash: reduce partials over r-tiles, normalize over OUT (warp = (b,c)) --------
__global__ void k_squash(const int use_part0, const int nparts, const float scale,
                         float* __restrict__ outp) {
    const int b = blockIdx.x;
    const int o = threadIdx.x;  // 32
    const int c = threadIdx.y;  // 32
    const float* part = use_part0 ? g_part0 : g_part;
    const size_t idx = (size_t)b * CO + c * ON + o;

    float s = 0.f;
    for (int p = 0; p < nparts; p++) s += part[(size_t)p * BN * CO + idx];
    s *= scale;

    float ss = s * s;
    #pragma unroll
    for (int sh = 16; sh; sh >>= 1) ss += __shfl_xor_sync(0xffffffffu, ss, sh);
    const float norm = sqrtf(ss);
    const float val = s * (ss / (1.f + ss)) / (norm + 1e-8f);

    float* dst = outp ? outp : g_v;
    dst[idx] = val;
}

extern "C" void kernel_launch(void* const* d_in, const int* in_sizes, int n_in,
                              void* d_out, int out_size) {
    const float* x = (const float*)d_in[0];  // [B, R, IN] f32
    const float* W = (const float*)d_in[1];  // [1, R, C, OUT, IN] f32
    float* out = (float*)d_out;              // [B, C, OUT] f32

    // iter 0: u_hat + s0 partials (uniform coupling 1/32)
    k1_uhat<<<dim3(4, K1_NRT), 256>>>(x, W);
    k_squash<<<BN, dim3(32, 32)>>>(1, K1_NRT, 1.f / 32.f, nullptr);  // v0 -> g_v
    // iter 1: b1 = 0 + u_hat.v0 ; s1
    k_route<<<dim3(BN, RT_NRT), 256>>>(1, 1);
    k_squash<<<BN, dim3(32, 32)>>>(0, RT_NRT, 1.f, nullptr);         // v1 -> g_v
    // iter 2: b2 = b1 + u_hat.v1 ; s2 ; v2 -> out
    k_route<<<dim3(BN, RT_NRT), 256>>>(0, 0);
    k_squash<<<BN, dim3(32, 32)>>>(0, RT_NRT, 1.f, out);
}

// round 2
// speedup vs baseline: 1.1393x; 1.1393x over previous
#include <cuda_runtime.h>

#define BN 64
#define RN 2048
#define CN 32
#define ON 32
#define INN 16
#define CO 1024      // CN*ON
#define CO4 256      // CO/4 (float4 granules per (b,r) row)

#define K1_RT 8
#define K1_NRT 256   // RN / K1_RT
#define RT_RT 64     // r per route block
#define RT_NRT 32    // RN / RT_RT
#define CH 8         // r per SMEM chunk in route
#define NCH 8        // chunks per route block (CH*NCH == RT_RT)

typedef unsigned long long u64;

// ---- scratch (device globals; allocation-free) ----
__device__ float4 g_uhat[(size_t)BN * RN * CO4];          // 512 MiB
__device__ float4 g_part0[(size_t)K1_NRT * BN * CO4];     // 64 MiB (s0 partials)
__device__ float4 g_part[(size_t)RT_NRT * BN * CO4];      // 8 MiB  (s1/s2 partials)
__device__ float  g_vsum[BN * CO];                        // running v0(+v1)

__device__ __forceinline__ u64 ffma2(u64 a, u64 b, u64 c) {
    u64 d;
    asm("fma.rn.f32x2 %0, %1, %2, %3;" : "=l"(d) : "l"(a), "l"(b), "l"(c));
    return d;
}
__device__ __forceinline__ float hsum2(u64 a) {
    float lo, hi;
    asm("mov.b64 {%0,%1}, %2;" : "=f"(lo), "=f"(hi) : "l"(a));
    return lo + hi;
}
__device__ __forceinline__ float dot4(float4 a, float4 b) {
    return a.x * b.x + a.y * b.y + a.z * b.z + a.w * b.w;
}
// XOR swizzle on 16B granules within a 4KB row (256 granules)
__device__ __forceinline__ int swz(int g) {
    return (g & 0xF8) | ((g & 7) ^ ((g >> 3) & 7));
}
__device__ __forceinline__ void cpa16(void* dst, const void* src) {
    unsigned d = (unsigned)__cvta_generic_to_shared(dst);
    asm volatile("cp.async.cg.shared.global [%0], [%1], 16;\n" ::"r"(d), "l"(src));
}
__device__ __forceinline__ void cpa_commit() {
    asm volatile("cp.async.commit_group;\n");
}
template <int N>
__device__ __forceinline__ void cpa_wait() {
    asm volatile("cp.async.wait_group %0;\n" ::"n"(N));
}

// -------- K1: u_hat[b,r,c,o] = sum_i W[r,c,o,i]*x[b,r,i]; fused s0 partials --------
// grid (4, 256): x = b-block of 16, y = r-tile of 8. 256 thr = 8 b-pairs x 32 lanes.
__global__ void __launch_bounds__(256) k1_uhat(const float* __restrict__ x,
                                               const float* __restrict__ W) {
    const int bb = blockIdx.x;
    const int rt = blockIdx.y;
    const int t  = threadIdx.x;
    const int bg = t >> 5;
    const int cl = t & 31;
    const int b0 = bb * 16 + bg * 2;
    const int b1 = b0 + 1;

    float s0a[8][4], s0b[8][4];
    #pragma unroll
    for (int k = 0; k < 8; k++)
        #pragma unroll
        for (int cc = 0; cc < 4; cc++) { s0a[k][cc] = 0.f; s0b[k][cc] = 0.f; }

    for (int rj = 0; rj < K1_RT; rj++) {
        const int r = rt * K1_RT + rj;
        // x rows as packed f32 pairs (8 pairs each)
        const ulonglong2* xu0 = (const ulonglong2*)(x + ((size_t)b0 * RN + r) * INN);
        const ulonglong2* xu1 = (const ulonglong2*)(x + ((size_t)b1 * RN + r) * INN);
        u64 xp0[8], xp1[8];
        #pragma unroll
        for (int q = 0; q < 4; q++) {
            ulonglong2 p0 = xu0[q], p1 = xu1[q];
            xp0[2 * q] = p0.x; xp0[2 * q + 1] = p0.y;
            xp1[2 * q] = p1.x; xp1[2 * q + 1] = p1.y;
        }

        const ulonglong2* wbase = (const ulonglong2*)(W + (size_t)r * CO * INN);
        float4* u0 = g_uhat + ((size_t)b0 * RN + r) * CO4;
        float4* u1 = g_uhat + ((size_t)b1 * RN + r) * CO4;

        #pragma unroll
        for (int k = 0; k < 8; k++) {
            const int cobase = cl * 4 + 128 * k;
            float4 o0, o1;
            #pragma unroll
            for (int cc = 0; cc < 4; cc++) {
                const ulonglong2* wr = wbase + (size_t)(cobase + cc) * 4;
                u64 w[8];
                #pragma unroll
                for (int q = 0; q < 4; q++) {
                    ulonglong2 wv = wr[q];
                    w[2 * q] = wv.x; w[2 * q + 1] = wv.y;
                }
                u64 a0 = 0ull, a1 = 0ull;
                #pragma unroll
                for (int p = 0; p < 8; p++) {
                    a0 = ffma2(w[p], xp0[p], a0);
                    a1 = ffma2(w[p], xp1[p], a1);
                }
                const float r0 = hsum2(a0), r1 = hsum2(a1);
                (&o0.x)[cc] = r0; (&o1.x)[cc] = r1;
                s0a[k][cc] += r0; s0b[k][cc] += r1;
            }
            u0[cobase >> 2] = o0;
            u1[cobase >> 2] = o1;
        }
    }

    float4* p0 = g_part0 + ((size_t)rt * BN + b0) * CO4;
    float4* p1 = g_part0 + ((size_t)rt * BN + b1) * CO4;
    #pragma unroll
    for (int k = 0; k < 8; k++) {
        const int g = cl + 32 * k;
        p0[g] = make_float4(s0a[k][0], s0a[k][1], s0a[k][2], s0a[k][3]);
        p1[g] = make_float4(s0b[k][0], s0b[k][1], s0b[k][2], s0b[k][3]);
    }
}

// -------- route pass: coef = softmax_c(u . vsum); s-partial accumulation --------
// grid (B, RT_NRT), 256 threads. cp.async double-buffered SMEM pipeline.
__global__ void __launch_bounds__(256) k_route() {
    __shared__ float4 ubuf[2][CH * CO4];   // 2 x 32 KB
    __shared__ float  scoef[CH * CN];      // 1 KB

    const int b  = blockIdx.x;
    const int rt = blockIdx.y;
    const int t  = threadIdx.x;
    const int w  = t >> 5;
    const int l  = t & 31;     // lane = capsule c in phase A
    const int gp = swz(t);     // this thread's swizzled granule (phase B + copy)
    const int myc = t >> 3;    // c index for phase B (co = 4t)

    // vsum for lane's capsule
    float4 vv[8];
    const float4* vp = (const float4*)g_vsum + (size_t)b * CO4 + l * 8;
    #pragma unroll
    for (int k = 0; k < 8; k++) vv[k] = vp[k];

    const float4* ubase = g_uhat + ((size_t)b * RN + rt * RT_RT) * CO4;

    // issue chunk 0
    #pragma unroll
    for (int q = 0; q < CH; q++)
        cpa16(&ubuf[0][q * CO4 + gp], ubase + (size_t)q * CO4 + t);
    cpa_commit();

    float4 acc = make_float4(0.f, 0.f, 0.f, 0.f);

    for (int ch = 0; ch < NCH; ch++) {
        const int nb = ch & 1;
        if (ch + 1 < NCH) {
            const float4* src = ubase + (size_t)(ch + 1) * CH * CO4;
            #pragma unroll
            for (int q = 0; q < CH; q++)
                cpa16(&ubuf[(ch + 1) & 1][q * CO4 + gp], src + (size_t)q * CO4 + t);
            cpa_commit();
            cpa_wait<1>();
        } else {
            cpa_wait<0>();
        }
        __syncthreads();

        // Phase A: warp w handles r_local = w; lane = c
        {
            float4 u[8];
            #pragma unroll
            for (int k = 0; k < 8; k++)
                u[k] = ubuf[nb][(w << 8) | (l << 3) | (k ^ (l & 7))];
            float d = 0.f;
            #pragma unroll
            for (int k = 0; k < 8; k++) d += dot4(u[k], vv[k]);

            float m = d;
            #pragma unroll
            for (int s = 16; s; s >>= 1) m = fmaxf(m, __shfl_xor_sync(0xffffffffu, m, s));
            const float e = __expf(d - m);
            float sum = e;
            #pragma unroll
            for (int s = 16; s; s >>= 1) sum += __shfl_xor_sync(0xffffffffu, sum, s);
            scoef[w * CN + l] = e / sum;
        }
        __syncthreads();

        // Phase B: thread owns co granule t (co = 4t..4t+3), accumulate over 8 r
        #pragma unroll
        for (int q = 0; q < CH; q++) {
            const float cf = scoef[q * CN + myc];
            const float4 u4 = ubuf[nb][q * CO4 + gp];
            acc.x += cf * u4.x; acc.y += cf * u4.y;
            acc.z += cf * u4.z; acc.w += cf * u4.w;
        }
        __syncthreads();  // protect ubuf[nb] before chunk ch+2 overwrites it
    }

    g_part[((size_t)rt * BN + b) * CO4 + t] = acc;
}

// -------- squash: reduce partials, normalize over OUT. MODE 0: vsum=v; 1: vsum+=v; 2: out --------
template <int NP, int MODE, bool USE_P0>
__global__ void k_squash(const float scale, float* __restrict__ outp) {
    const int b = blockIdx.x;
    const int o = threadIdx.x;                 // 32
    const int c = blockIdx.y * 8 + threadIdx.y; // 32 across 4 blocks
    const float4* part = USE_P0 ? g_part0 : g_part;
    const size_t stride = (size_t)BN * CO;      // floats per partial
    const size_t idx = (size_t)b * CO + c * ON + o;
    const float* pf = (const float*)part;

    float s = 0.f;
    #pragma unroll 16
    for (int p = 0; p < NP; p++) s += pf[p * stride + idx];
    s *= scale;

    float ss = s * s;
    #pragma unroll
    for (int sh = 16; sh; sh >>= 1) ss += __shfl_xor_sync(0xffffffffu, ss, sh);
    const float norm = sqrtf(ss);
    const float val = s * (ss / (1.f + ss)) / (norm + 1e-8f);

    if (MODE == 0) g_vsum[idx] = val;
    else if (MODE == 1) g_vsum[idx] += val;
    else outp[idx] = val;
}

__global__ void k_dummy() {}

extern "C" void kernel_launch(void* const* d_in, const int* in_sizes, int n_in,
                              void* d_out, int out_size) {
    const float* x = (const float*)d_in[0];  // [B, R, IN] f32
    const float* W = (const float*)d_in[1];  // [1, R, C, OUT, IN] f32
    float* out = (float*)d_out;              // [B, C, OUT] f32

    // iter 0: u_hat + s0 partials (uniform coupling 1/32); v0 -> vsum
    k1_uhat<<<dim3(4, K1_NRT), 256>>>(x, W);
    k_squash<K1_NRT, 0, true><<<dim3(BN, 4), dim3(32, 8)>>>(1.f / 32.f, nullptr);
    // iter 1: coef = softmax(u.v0); s1 -> v1; vsum += v1
    k_route<<<dim3(BN, RT_NRT), 256>>>();
    k_squash<RT_NRT, 1, false><<<dim3(BN, 4), dim3(32, 8)>>>(1.f, nullptr);
    // dummy shifts ncu (-s 5 -c 1) onto the second route pass
    k_dummy<<<1, 1>>>();
    // iter 2: coef = softmax(u.(v0+v1)); s2 -> v2 -> out
    k_route<<<dim3(BN, RT_NRT), 256>>>();
    k_squash<RT_NRT, 2, false><<<dim3(BN, 4), dim3(32, 8)>>>(1.f, out);
}

// round 3
// speedup vs baseline: 2.1220x; 1.8625x over previous
#include <cuda_runtime.h>

#define BN 64
#define RN 2048
#define CN 32
#define ON 32
#define INN 16
#define CO 1024      // CN*ON
#define CO4 256      // CO/4 (float4 granules per (b,r) row)

#define K1_RT 32
#define K1_NRT 64    // RN / K1_RT
#define RT_RT 64     // r per route block
#define RT_NRT 32    // RN / RT_RT
#define CH 8         // r per SMEM chunk in route
#define NCH 8        // chunks per route block (CH*NCH == RT_RT)

typedef unsigned long long u64;

// ---- scratch (device globals; allocation-free) ----
__device__ float4 g_uhat[(size_t)BN * RN * CO4];          // 512 MiB
__device__ float4 g_part0[(size_t)K1_NRT * BN * CO4];     // 16 MiB (s0 partials)
__device__ float4 g_part[(size_t)RT_NRT * BN * CO4];      // 8 MiB  (s1/s2 partials)
__device__ float  g_vsum[BN * CO];                        // running v0(+v1)

__device__ __forceinline__ u64 ffma2(u64 a, u64 b, u64 c) {
    u64 d;
    asm("fma.rn.f32x2 %0, %1, %2, %3;" : "=l"(d) : "l"(a), "l"(b), "l"(c));
    return d;
}
__device__ __forceinline__ float hsum2(u64 a) {
    float lo, hi;
    asm("mov.b64 {%0,%1}, %2;" : "=f"(lo), "=f"(hi) : "l"(a));
    return lo + hi;
}
__device__ __forceinline__ float dot4(float4 a, float4 b) {
    return a.x * b.x + a.y * b.y + a.z * b.z + a.w * b.w;
}
// XOR swizzle on 16B granules within a 4KB row (256 granules)
__device__ __forceinline__ int swz(int g) {
    return (g & 0xF8) | ((g & 7) ^ ((g >> 3) & 7));
}
__device__ __forceinline__ void cpa16(void* dst, const void* src) {
    unsigned d = (unsigned)__cvta_generic_to_shared(dst);
    asm volatile("cp.async.cg.shared.global [%0], [%1], 16;\n" ::"r"(d), "l"(src));
}
__device__ __forceinline__ void cpa_commit() {
    asm volatile("cp.async.commit_group;\n");
}
template <int N>
__device__ __forceinline__ void cpa_wait() {
    asm volatile("cp.async.wait_group %0;\n" ::"n"(N));
}

// -------- K1: u_hat[b,r,c,o] = sum_i W[r,c,o,i]*x[b,r,i]; fused s0 partials --------
// grid (4, 64): x = b-block of 16, y = r-tile of 32.
// 256 thr: warp w = (g, w2): g = b-quad (4 b's), w2 = co-half. Thread: 4 b x 16 co.
__global__ void __launch_bounds__(256) k1_uhat(const float* __restrict__ x,
                                               const float* __restrict__ W) {
    const int bblk = blockIdx.x;
    const int rt   = blockIdx.y;
    const int t  = threadIdx.x;
    const int w  = t >> 5;
    const int l  = t & 31;
    const int g  = w >> 1;   // b-quad
    const int w2 = w & 1;    // co-half
    const int b0 = bblk * 16 + g * 4;

    float s0[4][4][4];  // [b][k][cc]
    #pragma unroll
    for (int bi = 0; bi < 4; bi++)
        #pragma unroll
        for (int k = 0; k < 4; k++)
            #pragma unroll
            for (int cc = 0; cc < 4; cc++) s0[bi][k][cc] = 0.f;

    #pragma unroll 1
    for (int rj = 0; rj < K1_RT; rj++) {
        const int r = rt * K1_RT + rj;

        // x rows for the 4 b's (warp-uniform -> LDG broadcast)
        u64 xr[4][8];
        #pragma unroll
        for (int bi = 0; bi < 4; bi++) {
            const ulonglong2* xp =
                (const ulonglong2*)(x + ((size_t)(b0 + bi) * RN + r) * INN);
            #pragma unroll
            for (int q = 0; q < 4; q++) {
                ulonglong2 p = xp[q];
                xr[bi][2 * q] = p.x; xr[bi][2 * q + 1] = p.y;
            }
        }

        const ulonglong2* wb = (const ulonglong2*)(W + (size_t)r * CO * INN);
        float4* urow[4];
        #pragma unroll
        for (int bi = 0; bi < 4; bi++)
            urow[bi] = g_uhat + ((size_t)(b0 + bi) * RN + r) * CO4;

        #pragma unroll
        for (int k = 0; k < 4; k++) {
            const int gk = l + 32 * (4 * w2 + k);  // granule index (co = 4*gk)
            float4 o[4];
            #pragma unroll
            for (int cc = 0; cc < 4; cc++) {
                const ulonglong2* wr = wb + (size_t)(4 * gk + cc) * 4;
                u64 wv[8];
                #pragma unroll
                for (int q = 0; q < 4; q++) {
                    ulonglong2 v = wr[q];
                    wv[2 * q] = v.x; wv[2 * q + 1] = v.y;
                }
                #pragma unroll
                for (int bi = 0; bi < 4; bi++) {
                    u64 a = 0ull;
                    #pragma unroll
                    for (int p = 0; p < 8; p++) a = ffma2(wv[p], xr[bi][p], a);
                    const float val = hsum2(a);
                    (&o[bi].x)[cc] = val;
                    s0[bi][k][cc] += val;
                }
            }
            #pragma unroll
            for (int bi = 0; bi < 4; bi++) urow[bi][gk] = o[bi];
        }
    }

    #pragma unroll
    for (int bi = 0; bi < 4; bi++) {
        float4* p = g_part0 + ((size_t)rt * BN + b0 + bi) * CO4;
        #pragma unroll
        for (int k = 0; k < 4; k++)
            p[l + 32 * (4 * w2 + k)] =
                make_float4(s0[bi][k][0], s0[bi][k][1], s0[bi][k][2], s0[bi][k][3]);
    }
}

// -------- route pass: coef = softmax_c(u . vsum); s-partial accumulation --------
// grid (B, RT_NRT), 256 threads. cp.async double-buffered SMEM pipeline.
__global__ void __launch_bounds__(256) k_route() {
    __shared__ float4 ubuf[2][CH * CO4];   // 2 x 32 KB
    __shared__ float  scoef[CH * CN];      // 1 KB

    const int b  = blockIdx.x;
    const int rt = blockIdx.y;
    const int t  = threadIdx.x;
    const int w  = t >> 5;
    const int l  = t & 31;     // lane = capsule c in phase A
    const int gp = swz(t);     // this thread's swizzled granule (phase B + copy)
    const int myc = t >> 3;    // c index for phase B (co = 4t)

    // vsum for lane's capsule
    float4 vv[8];
    const float4* vp = (const float4*)g_vsum + (size_t)b * CO4 + l * 8;
    #pragma unroll
    for (int k = 0; k < 8; k++) vv[k] = vp[k];

    const float4* ubase = g_uhat + ((size_t)b * RN + rt * RT_RT) * CO4;

    // issue chunk 0
    #pragma unroll
    for (int q = 0; q < CH; q++)
        cpa16(&ubuf[0][q * CO4 + gp], ubase + (size_t)q * CO4 + t);
    cpa_commit();

    float4 acc = make_float4(0.f, 0.f, 0.f, 0.f);

    for (int ch = 0; ch < NCH; ch++) {
        const int nb = ch & 1;
        if (ch + 1 < NCH) {
            const float4* src = ubase + (size_t)(ch + 1) * CH * CO4;
            #pragma unroll
            for (int q = 0; q < CH; q++)
                cpa16(&ubuf[(ch + 1) & 1][q * CO4 + gp], src + (size_t)q * CO4 + t);
            cpa_commit();
            cpa_wait<1>();
        } else {
            cpa_wait<0>();
        }
        __syncthreads();

        // Phase A: warp w handles r_local = w; lane = c
        {
            float4 u[8];
            #pragma unroll
            for (int k = 0; k < 8; k++)
                u[k] = ubuf[nb][(w << 8) | (l << 3) | (k ^ (l & 7))];
            float d = 0.f;
            #pragma unroll
            for (int k = 0; k < 8; k++) d += dot4(u[k], vv[k]);

            float m = d;
            #pragma unroll
            for (int s = 16; s; s >>= 1) m = fmaxf(m, __shfl_xor_sync(0xffffffffu, m, s));
            const float e = __expf(d - m);
            float sum = e;
            #pragma unroll
            for (int s = 16; s; s >>= 1) sum += __shfl_xor_sync(0xffffffffu, sum, s);
            scoef[w * CN + l] = e / sum;
        }
        __syncthreads();

        // Phase B: thread owns co granule t (co = 4t..4t+3), accumulate over 8 r
        #pragma unroll
        for (int q = 0; q < CH; q++) {
            const float cf = scoef[q * CN + myc];
            const float4 u4 = ubuf[nb][q * CO4 + gp];
            acc.x += cf * u4.x; acc.y += cf * u4.y;
            acc.z += cf * u4.z; acc.w += cf * u4.w;
        }
        __syncthreads();  // protect ubuf[nb] before chunk ch+2 overwrites it
    }

    g_part[((size_t)rt * BN + b) * CO4 + t] = acc;
}

// -------- squash: reduce partials, normalize over OUT. MODE 0: vsum=v; 1: vsum+=v; 2: out --------
template <int NP, int MODE, bool USE_P0>
__global__ void k_squash(const float scale, float* __restrict__ outp) {
    const int b = blockIdx.x;
    const int o = threadIdx.x;                 // 32
    const int c = blockIdx.y * 8 + threadIdx.y; // 32 across 4 blocks
    const float4* part = USE_P0 ? g_part0 : g_part;
    const size_t stride = (size_t)BN * CO;      // floats per partial
    const size_t idx = (size_t)b * CO + c * ON + o;
    const float* pf = (const float*)part;

    float s = 0.f;
    #pragma unroll 16
    for (int p = 0; p < NP; p++) s += pf[p * stride + idx];
    s *= scale;

    float ss = s * s;
    #pragma unroll
    for (int sh = 16; sh; sh >>= 1) ss += __shfl_xor_sync(0xffffffffu, ss, sh);
    const float norm = sqrtf(ss);
    const float val = s * (ss / (1.f + ss)) / (norm + 1e-8f);

    if (MODE == 0) g_vsum[idx] = val;
    else if (MODE == 1) g_vsum[idx] += val;
    else outp[idx] = val;
}

__global__ void k_dummy() {}

extern "C" void kernel_launch(void* const* d_in, const int* in_sizes, int n_in,
                              void* d_out, int out_size) {
    const float* x = (const float*)d_in[0];  // [B, R, IN] f32
    const float* W = (const float*)d_in[1];  // [1, R, C, OUT, IN] f32
    float* out = (float*)d_out;              // [B, C, OUT] f32

    // idx0: u_hat + s0 partials (uniform coupling 1/32)
    k1_uhat<<<dim3(4, K1_NRT), 256>>>(x, W);
    // idx1: v0 -> vsum
    k_squash<K1_NRT, 0, true><<<dim3(BN, 4), dim3(32, 8)>>>(1.f / 32.f, nullptr);
    // idx2: dummy so both idx3 and idx5 are k_route for ncu
    k_dummy<<<1, 1>>>();
    // idx3: coef = softmax(u.v0); s1 partials
    k_route<<<dim3(BN, RT_NRT), 256>>>();
    // idx4: v1; vsum += v1
    k_squash<RT_NRT, 1, false><<<dim3(BN, 4), dim3(32, 8)>>>(1.f, nullptr);
    // idx5: coef = softmax(u.(v0+v1)); s2 partials
    k_route<<<dim3(BN, RT_NRT), 256>>>();
    // idx6: v2 -> out
    k_squash<RT_NRT, 2, false><<<dim3(BN, 4), dim3(32, 8)>>>(1.f, out);
}

// round 4
// speedup vs baseline: 4.4462x; 2.0952x over previous
#include <cuda_runtime.h>

#define BN 64
#define RN 2048
#define CN 32
#define ON 32
#define INN 16
#define CO 1024      // CN*ON
#define CO4 256      // CO/4

#define K1_R 16      // r per k1 block
#define K1_NRT 128   // RN / K1_R
#define RT_RT 64     // r per route block
#define RT_NRT 32    // RN / RT_RT
#define CH 8         // r per SMEM chunk in route
#define NCH 8        // chunks per route block

typedef unsigned long long u64;

// ---- scratch (device globals; allocation-free) ----
__device__ float4 g_uhat[(size_t)BN * RN * CO4];          // 512 MiB
__device__ float4 g_part0[(size_t)K1_NRT * BN * CO4];     // 32 MiB (s0 partials)
__device__ float4 g_part[(size_t)RT_NRT * BN * CO4];      // 8 MiB  (s1/s2 partials)
__device__ float  g_vsum[BN * CO];                        // running v0(+v1)

__device__ __forceinline__ u64 ffma2(u64 a, u64 b, u64 c) {
    u64 d;
    asm("fma.rn.f32x2 %0, %1, %2, %3;" : "=l"(d) : "l"(a), "l"(b), "l"(c));
    return d;
}
__device__ __forceinline__ float hsum2(u64 a) {
    float lo, hi;
    asm("mov.b64 {%0,%1}, %2;" : "=f"(lo), "=f"(hi) : "l"(a));
    return lo + hi;
}
__device__ __forceinline__ float dot4(float4 a, float4 b) {
    return a.x * b.x + a.y * b.y + a.z * b.z + a.w * b.w;
}
__device__ __forceinline__ int swz(int g) {   // route kernel swizzle (unchanged)
    return (g & 0xF8) | ((g & 7) ^ ((g >> 3) & 7));
}
// k1 W-buffer swizzle: 16B granule G -> conflict-free placement (byte offset)
__device__ __forceinline__ int wswz(int G) {
    return ((G >> 3) << 7) + (((G & 7) ^ ((G >> 3) & 7)) << 4);
}
__device__ __forceinline__ void cpa16(void* dst, const void* src) {
    unsigned d = (unsigned)__cvta_generic_to_shared(dst);
    asm volatile("cp.async.cg.shared.global [%0], [%1], 16;\n" ::"r"(d), "l"(src));
}
__device__ __forceinline__ void cpa_commit() {
    asm volatile("cp.async.commit_group;\n");
}
template <int N>
__device__ __forceinline__ void cpa_wait() {
    asm volatile("cp.async.wait_group %0;\n" ::"n"(N));
}
__device__ __forceinline__ void lds_v2u64(u64& a, u64& b, const void* p) {
    unsigned s = (unsigned)__cvta_generic_to_shared(p);
    asm volatile("ld.shared.v2.u64 {%0,%1}, [%2];" : "=l"(a), "=l"(b) : "r"(s));
}

// ================= K1: u_hat GEMM, SMEM-staged W, fused s0 partials =================
// grid (2, 128): x = co-half (512 co), y = r-tile (16 r). 256 threads.
// Thread owns co pair (2t, 2t+1) within the half; loops all 64 b per r.
// SMEM (dynamic, 200 KB): s0s[64][512] | Wbuf[2][32KB] | xbuf[2][4KB]
__global__ void __launch_bounds__(256) k1_uhat(const float* __restrict__ x,
                                               const float* __restrict__ W) {
    extern __shared__ float sm[];
    float* s0s   = sm;                    // 32768 floats (128 KB)
    float* wbuf0 = sm + 32768;            // 8192 floats (32 KB)
    float* wbuf1 = wbuf0 + 8192;
    float* xbuf0 = wbuf1 + 8192;          // 1024 floats (4 KB)
    float* xbuf1 = xbuf0 + 1024;

    const int half = blockIdx.x;
    const int rt   = blockIdx.y;
    const int t    = threadIdx.x;

    // zero s0 accumulator tile
    #pragma unroll
    for (int i = 0; i < 128; i++) s0s[t + 256 * i] = 0.f;

    const float* Wbase = W + (size_t)rt * K1_R * CO * INN + (size_t)half * 512 * INN;
    const float* xbase = x + rt * K1_R * INN;

    // stage r-slice into (wb, xb): W 32KB (8 granules/thread, swizzled), x 4KB (1/thread)
    auto stage = [&](int rr, float* wb, float* xb) {
        const float* wsrc = Wbase + (size_t)rr * CO * INN;
        #pragma unroll
        for (int k = 0; k < 8; k++) {
            const int G = t + 256 * k;
            cpa16((char*)wb + wswz(G), wsrc + 4 * G);
        }
        const int b = t >> 2, q = t & 3;
        cpa16(xb + 16 * b + 4 * q, xbase + ((size_t)b * RN + rr) * INN + 4 * q);
        cpa_commit();
    };

    stage(0, wbuf0, xbuf0);

    float* uout = (float*)g_uhat + (size_t)(rt * K1_R) * CO + half * 512 + 2 * t;

    for (int rr = 0; rr < K1_R; rr++) {
        float* wb = (rr & 1) ? wbuf1 : wbuf0;
        float* xb = (rr & 1) ? xbuf1 : xbuf0;
        cpa_wait<0>();
        __syncthreads();
        if (rr + 1 < K1_R)
            stage(rr + 1, (rr & 1) ? wbuf0 : wbuf1, (rr & 1) ? xbuf0 : xbuf1);

        // thread's two W rows: chunks j=0..7 of the 128B at 128*t (swizzled)
        u64 w[16];
        #pragma unroll
        for (int j = 0; j < 8; j++)
            lds_v2u64(w[2 * j], w[2 * j + 1],
                      (char*)wb + 128 * t + 16 * (j ^ (t & 7)));

        float* up = uout + (size_t)rr * CO;
        float* s0p = s0s + 2 * t;

        #pragma unroll 2
        for (int b = 0; b < 64; b++) {
            u64 xa[8];
            #pragma unroll
            for (int q = 0; q < 4; q++)
                lds_v2u64(xa[2 * q], xa[2 * q + 1], xb + 16 * b + 4 * q);

            u64 a0 = 0ull, a1 = 0ull;
            #pragma unroll
            for (int p = 0; p < 8; p++) {
                a0 = ffma2(w[p], xa[p], a0);
                a1 = ffma2(w[8 + p], xa[p], a1);
            }
            const float u0 = hsum2(a0), u1 = hsum2(a1);

            *(float2*)(up + (size_t)b * RN * CO) = make_float2(u0, u1);

            float2 s = *(float2*)(s0p + 512 * b);
            s.x += u0; s.y += u1;
            *(float2*)(s0p + 512 * b) = s;
        }
    }

    // write s0 partials: [rt][b][co] with our co-half slice
    __syncthreads();
    const float4* s4 = (const float4*)s0s;
    #pragma unroll
    for (int i = 0; i < 32; i++) {
        const int g = t + 256 * i;          // g = b*128 + c4
        const int b = g >> 7, c4 = g & 127;
        g_part0[(size_t)(rt * BN + b) * CO4 + half * 128 + c4] = s4[g];
    }
}

// ========== route pass: coef = softmax_c(u . vsum); s-partial accumulation ==========
__global__ void __launch_bounds__(256) k_route() {
    __shared__ float4 ubuf[2][CH * CO4];   // 2 x 32 KB
    __shared__ float  scoef[CH * CN];      // 1 KB

    const int b  = blockIdx.x;
    const int rt = blockIdx.y;
    const int t  = threadIdx.x;
    const int w  = t >> 5;
    const int l  = t & 31;     // lane = capsule c in phase A
    const int gp = swz(t);
    const int myc = t >> 3;

    float4 vv[8];
    const float4* vp = (const float4*)g_vsum + (size_t)b * CO4 + l * 8;
    #pragma unroll
    for (int k = 0; k < 8; k++) vv[k] = vp[k];

    const float4* ubase = g_uhat + ((size_t)b * RN + rt * RT_RT) * CO4;

    #pragma unroll
    for (int q = 0; q < CH; q++)
        cpa16(&ubuf[0][q * CO4 + gp], ubase + (size_t)q * CO4 + t);
    cpa_commit();

    float4 acc = make_float4(0.f, 0.f, 0.f, 0.f);

    for (int ch = 0; ch < NCH; ch++) {
        const int nb = ch & 1;
        if (ch + 1 < NCH) {
            const float4* src = ubase + (size_t)(ch + 1) * CH * CO4;
            #pragma unroll
            for (int q = 0; q < CH; q++)
                cpa16(&ubuf[(ch + 1) & 1][q * CO4 + gp], src + (size_t)q * CO4 + t);
            cpa_commit();
            cpa_wait<1>();
        } else {
            cpa_wait<0>();
        }
        __syncthreads();

        {
            float4 u[8];
            #pragma unroll
            for (int k = 0; k < 8; k++)
                u[k] = ubuf[nb][(w << 8) | (l << 3) | (k ^ (l & 7))];
            float d = 0.f;
            #pragma unroll
            for (int k = 0; k < 8; k++) d += dot4(u[k], vv[k]);

            float m = d;
            #pragma unroll
            for (int s = 16; s; s >>= 1) m = fmaxf(m, __shfl_xor_sync(0xffffffffu, m, s));
            const float e = __expf(d - m);
            float sum = e;
            #pragma unroll
            for (int s = 16; s; s >>= 1) sum += __shfl_xor_sync(0xffffffffu, sum, s);
            scoef[w * CN + l] = e / sum;
        }
        __syncthreads();

        #pragma unroll
        for (int q = 0; q < CH; q++) {
            const float cf = scoef[q * CN + myc];
            const float4 u4 = ubuf[nb][q * CO4 + gp];
            acc.x += cf * u4.x; acc.y += cf * u4.y;
            acc.z += cf * u4.z; acc.w += cf * u4.w;
        }
        __syncthreads();
    }

    g_part[((size_t)rt * BN + b) * CO4 + t] = acc;
}

// ===== squash: reduce partials, normalize over OUT. MODE 0: vsum=v; 1: +=; 2: out =====
template <int NP, int MODE, bool USE_P0>
__global__ void k_squash(const float scale, float* __restrict__ outp) {
    const int b = blockIdx.x;
    const int o = threadIdx.x;
    const int c = blockIdx.y * 8 + threadIdx.y;
    const float4* part = USE_P0 ? g_part0 : g_part;
    const size_t stride = (size_t)BN * CO;
    const size_t idx = (size_t)b * CO + c * ON + o;
    const float* pf = (const float*)part;

    float s = 0.f;
    #pragma unroll 16
    for (int p = 0; p < NP; p++) s += pf[p * stride + idx];
    s *= scale;

    float ss = s * s;
    #pragma unroll
    for (int sh = 16; sh; sh >>= 1) ss += __shfl_xor_sync(0xffffffffu, ss, sh);
    const float norm = sqrtf(ss);
    const float val = s * (ss / (1.f + ss)) / (norm + 1e-8f);

    if (MODE == 0) g_vsum[idx] = val;
    else if (MODE == 1) g_vsum[idx] += val;
    else outp[idx] = val;
}

__global__ void k_dummy() {}

extern "C" void kernel_launch(void* const* d_in, const int* in_sizes, int n_in,
                              void* d_out, int out_size) {
    const float* x = (const float*)d_in[0];  // [B, R, IN] f32
    const float* W = (const float*)d_in[1];  // [1, R, C, OUT, IN] f32
    float* out = (float*)d_out;              // [B, C, OUT] f32

    const int k1_smem = (32768 + 2 * 8192 + 2 * 1024) * 4;  // 200 KB
    cudaFuncSetAttribute(k1_uhat, cudaFuncAttributeMaxDynamicSharedMemorySize, k1_smem);

    // idx0-2: dummies so ncu's sampled launch (idx3) is k1_uhat
    k_dummy<<<1, 1>>>();
    k_dummy<<<1, 1>>>();
    k_dummy<<<1, 1>>>();
    // idx3: u_hat + s0 partials
    k1_uhat<<<dim3(2, K1_NRT), 256, k1_smem>>>(x, W);
    // v0 -> vsum
    k_squash<K1_NRT, 0, true><<<dim3(BN, 4), dim3(32, 8)>>>(1.f / 32.f, nullptr);
    // coef = softmax(u.v0); s1 partials
    k_route<<<dim3(BN, RT_NRT), 256>>>();
    // v1; vsum += v1
    k_squash<RT_NRT, 1, false><<<dim3(BN, 4), dim3(32, 8)>>>(1.f, nullptr);
    // coef = softmax(u.(v0+v1)); s2 partials
    k_route<<<dim3(BN, RT_NRT), 256>>>();
    // v2 -> out
    k_squash<RT_NRT, 2, false><<<dim3(BN, 4), dim3(32, 8)>>>(1.f, out);
}

// round 5
// speedup vs baseline: 5.5277x; 1.2433x over previous
#include <cuda_runtime.h>
#include <cuda_fp16.h>

#define BN 64
#define RN 2048
#define CN 32
#define ON 32
#define INN 16
#define CO 1024      // CN*ON
#define CO4 256      // CO/4
#define COH 512      // CO/2 (half2 per (b,r) row)
#define COG 128      // CO/8 (16B granules of half per row)

#define K1_R 16      // r per k1 block
#define K1_NRT 128   // RN / K1_R
#define RT_RT 64     // r per route block
#define RT_NRT 32    // RN / RT_RT
#define CH 8         // r per SMEM chunk in route
#define NCH 8        // chunks per route block

typedef unsigned long long u64;

// ---- scratch (device globals; allocation-free) ----
__device__ __half2 g_uhat[(size_t)BN * RN * COH];         // 256 MiB (fp16 u_hat)
__device__ float4 g_part0[(size_t)K1_NRT * BN * CO4];     // 32 MiB (s0 partials)
__device__ float4 g_part[(size_t)RT_NRT * BN * CO4];      // 8 MiB  (s1/s2 partials)
__device__ float  g_vsum[BN * CO];                        // running v0(+v1)

__device__ __forceinline__ u64 ffma2(u64 a, u64 b, u64 c) {
    u64 d;
    asm("fma.rn.f32x2 %0, %1, %2, %3;" : "=l"(d) : "l"(a), "l"(b), "l"(c));
    return d;
}
__device__ __forceinline__ float hsum2(u64 a) {
    float lo, hi;
    asm("mov.b64 {%0,%1}, %2;" : "=f"(lo), "=f"(hi) : "l"(a));
    return lo + hi;
}
// 16B-granule XOR swizzle (distinct slot%8 within any 8 consecutive/strided set)
__device__ __forceinline__ int swz(int g) {
    return (g & ~7) | ((g & 7) ^ ((g >> 3) & 7));
}
// k1 W-buffer swizzle: 16B granule G -> byte offset
__device__ __forceinline__ int wswz(int G) {
    return ((G >> 3) << 7) + (((G & 7) ^ ((G >> 3) & 7)) << 4);
}
__device__ __forceinline__ void cpa16(void* dst, const void* src) {
    unsigned d = (unsigned)__cvta_generic_to_shared(dst);
    asm volatile("cp.async.cg.shared.global [%0], [%1], 16;\n" ::"r"(d), "l"(src));
}
__device__ __forceinline__ void cpa_commit() {
    asm volatile("cp.async.commit_group;\n");
}
template <int N>
__device__ __forceinline__ void cpa_wait() {
    asm volatile("cp.async.wait_group %0;\n" ::"n"(N));
}
__device__ __forceinline__ void lds_v2u64(u64& a, u64& b, const void* p) {
    unsigned s = (unsigned)__cvta_generic_to_shared(p);
    asm volatile("ld.shared.v2.u64 {%0,%1}, [%2];" : "=l"(a), "=l"(b) : "r"(s));
}

// ================= K1: u_hat GEMM, SMEM-staged W, fused s0 partials =================
// grid (2, 128): x = co-half (512 co), y = r-tile (16 r). 256 threads.
// Thread owns co pair (2t, 2t+1) within its half; loops all 64 b per r.
__global__ void __launch_bounds__(256) k1_uhat(const float* __restrict__ x,
                                               const float* __restrict__ W) {
    extern __shared__ float sm[];
    float* s0s   = sm;                    // 32768 floats (128 KB)
    float* wbuf0 = sm + 32768;            // 8192 floats (32 KB)
    float* wbuf1 = wbuf0 + 8192;
    float* xbuf0 = wbuf1 + 8192;          // 1024 floats (4 KB)
    float* xbuf1 = xbuf0 + 1024;

    const int half = blockIdx.x;
    const int rt   = blockIdx.y;
    const int t    = threadIdx.x;

    #pragma unroll
    for (int i = 0; i < 128; i++) s0s[t + 256 * i] = 0.f;

    const float* Wbase = W + (size_t)rt * K1_R * CO * INN + (size_t)half * 512 * INN;
    const float* xbase = x + rt * K1_R * INN;

    auto stage = [&](int rr, float* wb, float* xb) {
        const float* wsrc = Wbase + (size_t)rr * CO * INN;
        #pragma unroll
        for (int k = 0; k < 8; k++) {
            const int G = t + 256 * k;
            cpa16((char*)wb + wswz(G), wsrc + 4 * G);
        }
        const int b = t >> 2, q = t & 3;
        cpa16(xb + 16 * b + 4 * q, xbase + ((size_t)b * RN + rr) * INN + 4 * q);
        cpa_commit();
    };

    stage(0, wbuf0, xbuf0);

    __half2* uout = g_uhat + (size_t)(rt * K1_R) * COH + half * 256 + t;

    for (int rr = 0; rr < K1_R; rr++) {
        float* wb = (rr & 1) ? wbuf1 : wbuf0;
        float* xb = (rr & 1) ? xbuf1 : xbuf0;
        cpa_wait<0>();
        __syncthreads();
        if (rr + 1 < K1_R)
            stage(rr + 1, (rr & 1) ? wbuf0 : wbuf1, (rr & 1) ? xbuf0 : xbuf1);

        u64 w[16];
        #pragma unroll
        for (int j = 0; j < 8; j++)
            lds_v2u64(w[2 * j], w[2 * j + 1],
                      (char*)wb + 128 * t + 16 * (j ^ (t & 7)));

        __half2* up = uout + (size_t)rr * COH;
        float* s0p = s0s + 2 * t;

        #pragma unroll 2
        for (int b = 0; b < 64; b++) {
            u64 xa[8];
            #pragma unroll
            for (int q = 0; q < 4; q++)
                lds_v2u64(xa[2 * q], xa[2 * q + 1], xb + 16 * b + 4 * q);

            u64 a0 = 0ull, a1 = 0ull;
            #pragma unroll
            for (int p = 0; p < 8; p++) {
                a0 = ffma2(w[p], xa[p], a0);
                a1 = ffma2(w[8 + p], xa[p], a1);
            }
            const float u0 = hsum2(a0), u1 = hsum2(a1);

            up[(size_t)b * RN * COH] = __floats2half2_rn(u0, u1);

            float2 s = *(float2*)(s0p + 512 * b);
            s.x += u0; s.y += u1;
            *(float2*)(s0p + 512 * b) = s;
        }
    }

    __syncthreads();
    const float4* s4 = (const float4*)s0s;
    #pragma unroll
    for (int i = 0; i < 32; i++) {
        const int g = t + 256 * i;          // g = b*128 + c4
        const int b = g >> 7, c4 = g & 127;
        g_part0[(size_t)(rt * BN + b) * CO4 + half * 128 + c4] = s4[g];
    }
}

// ========== route pass (fp16 u_hat): coef = softmax_c(u.vsum); s partials ==========
// grid (B, RT_NRT), 256 threads. Chunk = 8 r x 2KB (half), double-buffered.
__global__ void __launch_bounds__(256) k_route() {
    __shared__ uint4 ubuf[2][CH * COG];    // 2 x 16 KB
    __shared__ float scoef[CH * CN];       // 1 KB

    const int b  = blockIdx.x;
    const int rt = blockIdx.y;
    const int t  = threadIdx.x;
    const int w  = t >> 5;
    const int l  = t & 31;     // lane = capsule c in phase A
    const int myc = t >> 3;    // c for phase B (co = 4t)

    // vsum (f32) for lane's capsule: 32 floats
    float vvf[32];
    {
        const float4* vp = (const float4*)g_vsum + (size_t)b * CO4 + l * 8;
        #pragma unroll
        for (int k = 0; k < 8; k++) *(float4*)(vvf + 4 * k) = vp[k];
    }

    const uint4* ubase = (const uint4*)g_uhat + ((size_t)b * RN + rt * RT_RT) * COG;

    // copy: thread handles granules G = t + 256k (k=0..3): r = G>>7, col = G&127
    auto stage = [&](int ch, int buf) {
        const uint4* src = ubase + (size_t)ch * CH * COG;
        #pragma unroll
        for (int k = 0; k < 4; k++) {
            const int G = t + 256 * k;
            const int r = G >> 7, col = G & 127;
            cpa16(&ubuf[buf][r * COG + swz(col)], src + r * COG + col);
        }
        cpa_commit();
    };

    stage(0, 0);

    float4 acc = make_float4(0.f, 0.f, 0.f, 0.f);

    for (int ch = 0; ch < NCH; ch++) {
        const int nb = ch & 1;
        if (ch + 1 < NCH) { stage(ch + 1, (ch + 1) & 1); cpa_wait<1>(); }
        else              { cpa_wait<0>(); }
        __syncthreads();

        // Phase A: warp w -> r_local = w; lane l = c reads co 32l..32l+31
        {
            float d = 0.f;
            #pragma unroll
            for (int k = 0; k < 4; k++) {
                const uint4 g = ubuf[nb][w * COG + swz(4 * l + k)];
                const float2 f0 = __half22float2(*(const __half2*)&g.x);
                const float2 f1 = __half22float2(*(const __half2*)&g.y);
                const float2 f2 = __half22float2(*(const __half2*)&g.z);
                const float2 f3 = __half22float2(*(const __half2*)&g.w);
                const float* vp = vvf + 8 * k;
                d += f0.x * vp[0] + f0.y * vp[1] + f1.x * vp[2] + f1.y * vp[3]
                   + f2.x * vp[4] + f2.y * vp[5] + f3.x * vp[6] + f3.y * vp[7];
            }
            float m = d;
            #pragma unroll
            for (int s = 16; s; s >>= 1) m = fmaxf(m, __shfl_xor_sync(0xffffffffu, m, s));
            const float e = __expf(d - m);
            float sum = e;
            #pragma unroll
            for (int s = 16; s; s >>= 1) sum += __shfl_xor_sync(0xffffffffu, sum, s);
            scoef[w * CN + l] = e / sum;
        }
        __syncthreads();

        // Phase B: thread owns co 4t..4t+3 (8B = half of granule t>>1), over 8 r
        {
            const int gB = swz(t >> 1);
            const int sub = (t & 1) * 8;
            #pragma unroll
            for (int q = 0; q < CH; q++) {
                const float cf = scoef[q * CN + myc];
                const uint2 v = *(const uint2*)((const char*)&ubuf[nb][q * COG + gB] + sub);
                const float2 f0 = __half22float2(*(const __half2*)&v.x);
                const float2 f1 = __half22float2(*(const __half2*)&v.y);
                acc.x += cf * f0.x; acc.y += cf * f0.y;
                acc.z += cf * f1.x; acc.w += cf * f1.y;
            }
        }
        __syncthreads();
    }

    g_part[((size_t)rt * BN + b) * CO4 + t] = acc;
}

// ===== squash: reduce partials, normalize over OUT. MODE 0: vsum=v; 1: +=; 2: out =====
template <int NP, int MODE, bool USE_P0>
__global__ void k_squash(const float scale, float* __restrict__ outp) {
    const int b = blockIdx.x;
    const int o = threadIdx.x;
    const int c = blockIdx.y * 8 + threadIdx.y;
    const float4* part = USE_P0 ? g_part0 : g_part;
    const size_t stride = (size_t)BN * CO;
    const size_t idx = (size_t)b * CO + c * ON + o;
    const float* pf = (const float*)part;

    float s = 0.f;
    #pragma unroll 16
    for (int p = 0; p < NP; p++) s += pf[p * stride + idx];
    s *= scale;

    float ss = s * s;
    #pragma unroll
    for (int sh = 16; sh; sh >>= 1) ss += __shfl_xor_sync(0xffffffffu, ss, sh);
    const float norm = sqrtf(ss);
    const float val = s * (ss / (1.f + ss)) / (norm + 1e-8f);

    if (MODE == 0) g_vsum[idx] = val;
    else if (MODE == 1) g_vsum[idx] += val;
    else outp[idx] = val;
}

__global__ void k_dummy() {}

extern "C" void kernel_launch(void* const* d_in, const int* in_sizes, int n_in,
                              void* d_out, int out_size) {
    const float* x = (const float*)d_in[0];  // [B, R, IN] f32
    const float* W = (const float*)d_in[1];  // [1, R, C, OUT, IN] f32
    float* out = (float*)d_out;              // [B, C, OUT] f32

    const int k1_smem = (32768 + 2 * 8192 + 2 * 1024) * 4;  // 200 KB
    cudaFuncSetAttribute(k1_uhat, cudaFuncAttributeMaxDynamicSharedMemorySize, k1_smem);

    // idx0-2: dummies so ncu's sampled launch (idx3) is k1_uhat
    k_dummy<<<1, 1>>>();
    k_dummy<<<1, 1>>>();
    k_dummy<<<1, 1>>>();
    // idx3: u_hat (fp16) + s0 partials
    k1_uhat<<<dim3(2, K1_NRT), 256, k1_smem>>>(x, W);
    // v0 -> vsum
    k_squash<K1_NRT, 0, true><<<dim3(BN, 4), dim3(32, 8)>>>(1.f / 32.f, nullptr);
    // coef = softmax(u.v0); s1 partials
    k_route<<<dim3(BN, RT_NRT), 256>>>();
    // v1; vsum += v1
    k_squash<RT_NRT, 1, false><<<dim3(BN, 4), dim3(32, 8)>>>(1.f, nullptr);
    // coef = softmax(u.(v0+v1)); s2 partials
    k_route<<<dim3(BN, RT_NRT), 256>>>();
    // v2 -> out
    k_squash<RT_NRT, 2, false><<<dim3(BN, 4), dim3(32, 8)>>>(1.f, out);
}

// round 6
// speedup vs baseline: 5.5319x; 1.0008x over previous
#include <cuda_runtime.h>
#include <cuda_fp16.h>

#define BN 64
#define RN 2048
#define CN 32
#define ON 32
#define INN 16
#define CO 1024      // CN*ON
#define CO4 256      // CO/4
#define COH 512      // CO/2 (half2 per (b,r) row)
#define COG 128      // CO/8 (16B granules of half per row)

#define K1_R 16      // r per k1 block
#define K1_NRT 128   // RN / K1_R
#define RT_RT 64     // r per route block
#define RT_NRT 32    // RN / RT_RT
#define CH 8         // r per SMEM chunk in route
#define NCH 8        // chunks per route block

typedef unsigned long long u64;

// ---- scratch (device globals; allocation-free) ----
__device__ __half2 g_uhat[(size_t)BN * RN * COH];         // 256 MiB (fp16 u_hat)
__device__ float4 g_part0[(size_t)K1_NRT * BN * CO4];     // 32 MiB (s0 partials)
__device__ float4 g_part[(size_t)RT_NRT * BN * CO4];      // 8 MiB  (s1/s2 partials)
__device__ float  g_vsum[BN * CO];                        // running v0(+v1)

__device__ __forceinline__ u64 ffma2(u64 a, u64 b, u64 c) {
    u64 d;
    asm("fma.rn.f32x2 %0, %1, %2, %3;" : "=l"(d) : "l"(a), "l"(b), "l"(c));
    return d;
}
__device__ __forceinline__ float hsum2(u64 a) {
    float lo, hi;
    asm("mov.b64 {%0,%1}, %2;" : "=f"(lo), "=f"(hi) : "l"(a));
    return lo + hi;
}
// 16B-granule XOR swizzle
__device__ __forceinline__ int swz(int g) {
    return (g & ~7) | ((g & 7) ^ ((g >> 3) & 7));
}
// k1 W-buffer swizzle: 16B granule G -> byte offset
__device__ __forceinline__ int wswz(int G) {
    return ((G >> 3) << 7) + (((G & 7) ^ ((G >> 3) & 7)) << 4);
}
__device__ __forceinline__ void cpa16(void* dst, const void* src) {
    unsigned d = (unsigned)__cvta_generic_to_shared(dst);
    asm volatile("cp.async.cg.shared.global [%0], [%1], 16;\n" ::"r"(d), "l"(src));
}
__device__ __forceinline__ void cpa_commit() {
    asm volatile("cp.async.commit_group;\n");
}
template <int N>
__device__ __forceinline__ void cpa_wait() {
    asm volatile("cp.async.wait_group %0;\n" ::"n"(N));
}
__device__ __forceinline__ void lds_v2u64(u64& a, u64& b, const void* p) {
    unsigned s = (unsigned)__cvta_generic_to_shared(p);
    asm volatile("ld.shared.v2.u64 {%0,%1}, [%2];" : "=l"(a), "=l"(b) : "r"(s));
}

// ================= K1: u_hat GEMM, SMEM-staged W, fused s0 partials =================
// grid (2, 128): x = co-half (512 co), y = r-tile (16 r). 512 threads:
// two b-groups (g2 = t>>8) of 32 b; thread owns co pair (2tt, 2tt+1), tt = t&255.
__global__ void __launch_bounds__(512) k1_uhat(const float* __restrict__ x,
                                               const float* __restrict__ W) {
    extern __shared__ float sm[];
    float* s0s   = sm;                    // 32768 floats (128 KB) [b][512co]
    float* wbuf0 = sm + 32768;            // 8192 floats (32 KB)
    float* wbuf1 = wbuf0 + 8192;
    float* xbuf0 = wbuf1 + 8192;          // 1024 floats (4 KB)
    float* xbuf1 = xbuf0 + 1024;

    const int half = blockIdx.x;
    const int rt   = blockIdx.y;
    const int t    = threadIdx.x;
    const int tt   = t & 255;   // co-pair index within half
    const int g2   = t >> 8;    // b-group (0: b 0..31, 1: b 32..63)
    const int bbase = g2 * 32;

    #pragma unroll
    for (int i = 0; i < 64; i++) s0s[t + 512 * i] = 0.f;

    const float* Wbase = W + (size_t)rt * K1_R * CO * INN + (size_t)half * 512 * INN;
    const float* xbase = x + rt * K1_R * INN;

    auto stage = [&](int rr, float* wb, float* xb) {
        const float* wsrc = Wbase + (size_t)rr * CO * INN;
        #pragma unroll
        for (int k = 0; k < 4; k++) {
            const int G = t + 512 * k;
            cpa16((char*)wb + wswz(G), wsrc + 4 * G);
        }
        if (t < 256) {
            const int b = t >> 2, q = t & 3;
            cpa16(xb + 16 * b + 4 * q, xbase + ((size_t)b * RN + rr) * INN + 4 * q);
        }
        cpa_commit();
    };

    stage(0, wbuf0, xbuf0);

    __half2* uout = g_uhat + (size_t)(rt * K1_R) * COH + half * 256 + tt;

    for (int rr = 0; rr < K1_R; rr++) {
        float* wb = (rr & 1) ? wbuf1 : wbuf0;
        float* xb = (rr & 1) ? xbuf1 : xbuf0;
        cpa_wait<0>();
        __syncthreads();
        if (rr + 1 < K1_R)
            stage(rr + 1, (rr & 1) ? wbuf0 : wbuf1, (rr & 1) ? xbuf0 : xbuf1);

        // thread's two W rows (granules 8tt..8tt+7, swizzled)
        u64 w[16];
        #pragma unroll
        for (int j = 0; j < 8; j++)
            lds_v2u64(w[2 * j], w[2 * j + 1],
                      (char*)wb + 128 * tt + 16 * (j ^ (tt & 7)));

        __half2* up = uout + (size_t)rr * COH;
        float* s0p = s0s + 2 * tt;

        #pragma unroll 2
        for (int bi = 0; bi < 32; bi++) {
            const int b = bbase + bi;
            u64 xa[8];
            #pragma unroll
            for (int q = 0; q < 4; q++)
                lds_v2u64(xa[2 * q], xa[2 * q + 1], xb + 16 * b + 4 * q);

            u64 a0 = 0ull, a1 = 0ull;
            #pragma unroll
            for (int p = 0; p < 8; p++) {
                a0 = ffma2(w[p], xa[p], a0);
                a1 = ffma2(w[8 + p], xa[p], a1);
            }
            const float u0 = hsum2(a0), u1 = hsum2(a1);

            up[(size_t)b * RN * COH] = __floats2half2_rn(u0, u1);

            float2 s = *(float2*)(s0p + 512 * b);
            s.x += u0; s.y += u1;
            *(float2*)(s0p + 512 * b) = s;
        }
    }

    __syncthreads();
    const float4* s4 = (const float4*)s0s;
    #pragma unroll
    for (int i = 0; i < 16; i++) {
        const int g = t + 512 * i;          // g = b*128 + c4
        const int b = g >> 7, c4 = g & 127;
        g_part0[(size_t)(rt * BN + b) * CO4 + half * 128 + c4] = s4[g];
    }
}

// ========== route pass (fp16 u_hat): coef = softmax_c(u.vsum); s partials ==========
// grid (B, RT_NRT), 256 threads. Chunk = 8 r x 2KB (half), double-buffered.
__global__ void __launch_bounds__(256) k_route() {
    __shared__ uint4 ubuf[2][CH * COG];    // 2 x 16 KB
    __shared__ float scoef[CH * CN];       // 1 KB

    const int b  = blockIdx.x;
    const int rt = blockIdx.y;
    const int t  = threadIdx.x;
    const int w  = t >> 5;
    const int l  = t & 31;     // lane = capsule c in phase A
    const int myc = t >> 3;    // c for phase B (co = 4t)

    float vvf[32];
    {
        const float4* vp = (const float4*)g_vsum + (size_t)b * CO4 + l * 8;
        #pragma unroll
        for (int k = 0; k < 8; k++) *(float4*)(vvf + 4 * k) = vp[k];
    }

    const uint4* ubase = (const uint4*)g_uhat + ((size_t)b * RN + rt * RT_RT) * COG;

    auto stage = [&](int ch, int buf) {
        const uint4* src = ubase + (size_t)ch * CH * COG;
        #pragma unroll
        for (int k = 0; k < 4; k++) {
            const int G = t + 256 * k;
            const int r = G >> 7, col = G & 127;
            cpa16(&ubuf[buf][r * COG + swz(col)], src + r * COG + col);
        }
        cpa_commit();
    };

    stage(0, 0);

    float4 acc = make_float4(0.f, 0.f, 0.f, 0.f);

    for (int ch = 0; ch < NCH; ch++) {
        const int nb = ch & 1;
        if (ch + 1 < NCH) { stage(ch + 1, (ch + 1) & 1); cpa_wait<1>(); }
        else              { cpa_wait<0>(); }
        __syncthreads();

        // Phase A: warp w -> r_local = w; lane l = c reads co 32l..32l+31
        {
            float d = 0.f;
            #pragma unroll
            for (int k = 0; k < 4; k++) {
                const uint4 g = ubuf[nb][w * COG + swz(4 * l + k)];
                const float2 f0 = __half22float2(*(const __half2*)&g.x);
                const float2 f1 = __half22float2(*(const __half2*)&g.y);
                const float2 f2 = __half22float2(*(const __half2*)&g.z);
                const float2 f3 = __half22float2(*(const __half2*)&g.w);
                const float* vp = vvf + 8 * k;
                d += f0.x * vp[0] + f0.y * vp[1] + f1.x * vp[2] + f1.y * vp[3]
                   + f2.x * vp[4] + f2.y * vp[5] + f3.x * vp[6] + f3.y * vp[7];
            }
            float m = d;
            #pragma unroll
            for (int s = 16; s; s >>= 1) m = fmaxf(m, __shfl_xor_sync(0xffffffffu, m, s));
            const float e = __expf(d - m);
            float sum = e;
            #pragma unroll
            for (int s = 16; s; s >>= 1) sum += __shfl_xor_sync(0xffffffffu, sum, s);
            scoef[w * CN + l] = e / sum;
        }
        __syncthreads();

        // Phase B: thread owns co 4t..4t+3 (8B = half of granule t>>1), over 8 r
        {
            const int gB = swz(t >> 1);
            const int sub = (t & 1) * 8;
            #pragma unroll
            for (int q = 0; q < CH; q++) {
                const float cf = scoef[q * CN + myc];
                const uint2 v = *(const uint2*)((const char*)&ubuf[nb][q * COG + gB] + sub);
                const float2 f0 = __half22float2(*(const __half2*)&v.x);
                const float2 f1 = __half22float2(*(const __half2*)&v.y);
                acc.x += cf * f0.x; acc.y += cf * f0.y;
                acc.z += cf * f1.x; acc.w += cf * f1.y;
            }
        }
        __syncthreads();
    }

    g_part[((size_t)rt * BN + b) * CO4 + t] = acc;
}

// ===== squash: reduce partials, normalize over OUT. MODE 0: vsum=v; 1: +=; 2: out =====
template <int NP, int MODE, bool USE_P0>
__global__ void k_squash(const float scale, float* __restrict__ outp) {
    const int b = blockIdx.x;
    const int o = threadIdx.x;
    const int c = blockIdx.y * 8 + threadIdx.y;
    const float4* part = USE_P0 ? g_part0 : g_part;
    const size_t stride = (size_t)BN * CO;
    const size_t idx = (size_t)b * CO + c * ON + o;
    const float* pf = (const float*)part;

    float s = 0.f;
    #pragma unroll 16
    for (int p = 0; p < NP; p++) s += pf[p * stride + idx];
    s *= scale;

    float ss = s * s;
    #pragma unroll
    for (int sh = 16; sh; sh >>= 1) ss += __shfl_xor_sync(0xffffffffu, ss, sh);
    const float norm = sqrtf(ss);
    const float val = s * (ss / (1.f + ss)) / (norm + 1e-8f);

    if (MODE == 0) g_vsum[idx] = val;
    else if (MODE == 1) g_vsum[idx] += val;
    else outp[idx] = val;
}

__global__ void k_dummy() {}

extern "C" void kernel_launch(void* const* d_in, const int* in_sizes, int n_in,
                              void* d_out, int out_size) {
    const float* x = (const float*)d_in[0];  // [B, R, IN] f32
    const float* W = (const float*)d_in[1];  // [1, R, C, OUT, IN] f32
    float* out = (float*)d_out;              // [B, C, OUT] f32

    const int k1_smem = (32768 + 2 * 8192 + 2 * 1024) * 4;  // 200 KB
    cudaFuncSetAttribute(k1_uhat, cudaFuncAttributeMaxDynamicSharedMemorySize, k1_smem);

    // idx0-2: dummies so ncu's sampled launch (idx3) is k1_uhat
    k_dummy<<<1, 1>>>();
    k_dummy<<<1, 1>>>();
    k_dummy<<<1, 1>>>();
    // idx3: u_hat (fp16) + s0 partials
    k1_uhat<<<dim3(2, K1_NRT), 512, k1_smem>>>(x, W);
    // v0 -> vsum
    k_squash<K1_NRT, 0, true><<<dim3(BN, 4), dim3(32, 8)>>>(1.f / 32.f, nullptr);
    // coef = softmax(u.v0); s1 partials
    k_route<<<dim3(BN, RT_NRT), 256>>>();
    // v1; vsum += v1
    k_squash<RT_NRT, 1, false><<<dim3(BN, 4), dim3(32, 8)>>>(1.f, nullptr);
    // coef = softmax(u.(v0+v1)); s2 partials
    k_route<<<dim3(BN, RT_NRT), 256>>>();
    // v2 -> out
    k_squash<RT_NRT, 2, false><<<dim3(BN, 4), dim3(32, 8)>>>(1.f, out);
}

// round 8
// speedup vs baseline: 6.0948x; 1.1018x over previous
#include <cuda_runtime.h>
#include <cuda_fp16.h>

#define BN 64
#define RN 2048
#define CN 32
#define ON 32
#define INN 16
#define CO 1024      // CN*ON
#define CO4 256      // CO/4
#define COH 512      // CO/2 (half2 per (b,r) row)
#define COG 128      // CO/8 (16B granules of half per row)

#define K1_R 16      // r per k1 block
#define K1_NRT 128   // RN / K1_R
#define RT_RT 64     // r per route block
#define RT_NRT 32    // RN / RT_RT
#define CH 8         // r per SMEM chunk in route
#define NCH 8        // chunks per route block

typedef unsigned long long u64;

// ---- scratch (device globals; allocation-free) ----
__device__ __half2 g_uhat[(size_t)BN * RN * COH];         // 256 MiB (fp16 u_hat)
__device__ float4 g_part0[(size_t)K1_NRT * BN * CO4];     // 32 MiB (s0 partials)
__device__ float4 g_part[(size_t)RT_NRT * BN * CO4];      // 8 MiB  (s1/s2 partials)
__device__ float  g_vsum[BN * CO];                        // running v0(+v1)

__device__ __forceinline__ u64 ffma2(u64 a, u64 b, u64 c) {
    u64 d;
    asm("fma.rn.f32x2 %0, %1, %2, %3;" : "=l"(d) : "l"(a), "l"(b), "l"(c));
    return d;
}
__device__ __forceinline__ float hsum2(u64 a) {
    float lo, hi;
    asm("mov.b64 {%0,%1}, %2;" : "=f"(lo), "=f"(hi) : "l"(a));
    return lo + hi;
}
// route-kernel 16B-granule XOR swizzle
__device__ __forceinline__ int swz(int g) {
    return (g & ~7) | ((g & 7) ^ ((g >> 3) & 7));
}
// k1 W-buffer swizzle: granule G -> byte offset.
// slot = (G&7) ^ ((G>>4)&7): conflict-free for writes (consecutive G) and
// reads (G = 16*tc + j, j fixed, tc 8-consecutive).
__device__ __forceinline__ int wswz(int G) {
    return ((G >> 3) << 7) | ((((G & 7) ^ ((G >> 4) & 7))) << 4);
}
__device__ __forceinline__ void cpa16(void* dst, const void* src) {
    unsigned d = (unsigned)__cvta_generic_to_shared(dst);
    asm volatile("cp.async.cg.shared.global [%0], [%1], 16;\n" ::"r"(d), "l"(src));
}
__device__ __forceinline__ void cpa_commit() {
    asm volatile("cp.async.commit_group;\n");
}
template <int N>
__device__ __forceinline__ void cpa_wait() {
    asm volatile("cp.async.wait_group %0;\n" ::"n"(N));
}
__device__ __forceinline__ void lds_v2u64(u64& a, u64& b, const void* p) {
    unsigned s = (unsigned)__cvta_generic_to_shared(p);
    asm volatile("ld.shared.v2.u64 {%0,%1}, [%2];" : "=l"(a), "=l"(b) : "r"(s));
}

// ================= K1: u_hat GEMM, SMEM-staged W, fused s0 partials =================
// grid (2, 128): x = co-half (512 co), y = r-tile (16 r). 512 threads:
// t = bg*128 + tc. bg = b-group (16 b), tc owns co quad 4tc..4tc+3.
__global__ void __launch_bounds__(512) k1_uhat(const float* __restrict__ x,
                                               const float* __restrict__ W) {
    extern __shared__ float sm[];
    float* s0s   = sm;                    // 32768 floats (128 KB) [b][512co]
    float* wbuf0 = sm + 32768;            // 8192 floats (32 KB)
    float* wbuf1 = wbuf0 + 8192;
    float* xbuf0 = wbuf1 + 8192;          // 1024 floats (4 KB)
    float* xbuf1 = xbuf0 + 1024;

    const int half = blockIdx.x;
    const int rt   = blockIdx.y;
    const int t    = threadIdx.x;
    const int tc   = t & 127;   // co-quad index within half
    const int bg   = t >> 7;    // b-group (16 b each)
    const int bbase = bg * 16;

    #pragma unroll
    for (int i = 0; i < 64; i++) s0s[t + 512 * i] = 0.f;

    const float* Wbase = W + (size_t)rt * K1_R * CO * INN + (size_t)half * 512 * INN;
    const float* xbase = x + rt * K1_R * INN;

    auto stage = [&](int rr, float* wb, float* xb) {
        const float* wsrc = Wbase + (size_t)rr * CO * INN;
        #pragma unroll
        for (int k = 0; k < 4; k++) {
            const int G = t + 512 * k;
            cpa16((char*)wb + wswz(G), wsrc + 4 * G);
        }
        if (t < 256) {
            const int b = t >> 2, q = t & 3;
            cpa16(xb + 16 * b + 4 * q, xbase + ((size_t)b * RN + rr) * INN + 4 * q);
        }
        cpa_commit();
    };

    stage(0, wbuf0, xbuf0);

    // half2-unit base: co quad -> half2 pair index 2*tc
    __half2* uout = g_uhat + (size_t)(rt * K1_R) * COH + half * 256 + 2 * tc;

    for (int rr = 0; rr < K1_R; rr++) {
        float* wb = (rr & 1) ? wbuf1 : wbuf0;
        float* xb = (rr & 1) ? xbuf1 : xbuf0;
        cpa_wait<0>();
        __syncthreads();
        if (rr + 1 < K1_R)
            stage(rr + 1, (rr & 1) ? wbuf0 : wbuf1, (rr & 1) ? xbuf0 : xbuf1);

        // thread's four W rows: granules 16tc..16tc+15 (swizzled)
        u64 w[4][8];
        #pragma unroll
        for (int cc = 0; cc < 4; cc++)
            #pragma unroll
            for (int q = 0; q < 4; q++)
                lds_v2u64(w[cc][2 * q], w[cc][2 * q + 1],
                          (char*)wb + wswz(16 * tc + 4 * cc + q));

        __half2* up = uout + (size_t)rr * COH;
        float* s0p = s0s + 4 * tc;

        #pragma unroll 2
        for (int bi = 0; bi < 16; bi++) {
            const int b = bbase + bi;
            u64 xa[8];
            #pragma unroll
            for (int q = 0; q < 4; q++)
                lds_v2u64(xa[2 * q], xa[2 * q + 1], xb + 16 * b + 4 * q);

            u64 a[4] = {0ull, 0ull, 0ull, 0ull};
            #pragma unroll
            for (int p = 0; p < 8; p++) {
                a[0] = ffma2(w[0][p], xa[p], a[0]);
                a[1] = ffma2(w[1][p], xa[p], a[1]);
                a[2] = ffma2(w[2][p], xa[p], a[2]);
                a[3] = ffma2(w[3][p], xa[p], a[3]);
            }
            const float u0 = hsum2(a[0]), u1 = hsum2(a[1]);
            const float u2 = hsum2(a[2]), u3 = hsum2(a[3]);

            uint2 pkt;
            *(__half2*)&pkt.x = __floats2half2_rn(u0, u1);
            *(__half2*)&pkt.y = __floats2half2_rn(u2, u3);
            *(uint2*)(up + (size_t)b * RN * COH) = pkt;

            float4 s = *(float4*)(s0p + 512 * b);
            s.x += u0; s.y += u1; s.z += u2; s.w += u3;
            *(float4*)(s0p + 512 * b) = s;
        }
    }

    __syncthreads();
    const float4* s4 = (const float4*)s0s;
    #pragma unroll
    for (int i = 0; i < 16; i++) {
        const int g = t + 512 * i;          // g = b*128 + c4
        const int b = g >> 7, c4 = g & 127;
        g_part0[(size_t)(rt * BN + b) * CO4 + half * 128 + c4] = s4[g];
    }
}

// ========== route pass (fp16 u_hat): coef = softmax_c(u.vsum); s partials ==========
// grid (B, RT_NRT), 256 threads. Chunk = 8 r x 2KB (half), double-buffered.
__global__ void __launch_bounds__(256) k_route() {
    __shared__ uint4 ubuf[2][CH * COG];    // 2 x 16 KB
    __shared__ float scoef[CH * CN];       // 1 KB

    const int b  = blockIdx.x;
    const int rt = blockIdx.y;
    const int t  = threadIdx.x;
    const int w  = t >> 5;
    const int l  = t & 31;     // lane = capsule c in phase A
    const int myc = t >> 3;    // c for phase B (co = 4t)

    float vvf[32];
    {
        const float4* vp = (const float4*)g_vsum + (size_t)b * CO4 + l * 8;
        #pragma unroll
        for (int k = 0; k < 8; k++) *(float4*)(vvf + 4 * k) = vp[k];
    }

    const uint4* ubase = (const uint4*)g_uhat + ((size_t)b * RN + rt * RT_RT) * COG;

    auto stage = [&](int ch, int buf) {
        const uint4* src = ubase + (size_t)ch * CH * COG;
        #pragma unroll
        for (int k = 0; k < 4; k++) {
            const int G = t + 256 * k;
            const int r = G >> 7, col = G & 127;
            cpa16(&ubuf[buf][r * COG + swz(col)], src + r * COG + col);
        }
        cpa_commit();
    };

    stage(0, 0);

    float4 acc = make_float4(0.f, 0.f, 0.f, 0.f);

    for (int ch = 0; ch < NCH; ch++) {
        const int nb = ch & 1;
        if (ch + 1 < NCH) { stage(ch + 1, (ch + 1) & 1); cpa_wait<1>(); }
        else              { cpa_wait<0>(); }
        __syncthreads();

        // Phase A: warp w -> r_local = w; lane l = c reads co 32l..32l+31
        {
            float d = 0.f;
            #pragma unroll
            for (int k = 0; k < 4; k++) {
                const uint4 g = ubuf[nb][w * COG + swz(4 * l + k)];
                const float2 f0 = __half22float2(*(const __half2*)&g.x);
                const float2 f1 = __half22float2(*(const __half2*)&g.y);
                const float2 f2 = __half22float2(*(const __half2*)&g.z);
                const float2 f3 = __half22float2(*(const __half2*)&g.w);
                const float* vp = vvf + 8 * k;
                d += f0.x * vp[0] + f0.y * vp[1] + f1.x * vp[2] + f1.y * vp[3]
                   + f2.x * vp[4] + f2.y * vp[5] + f3.x * vp[6] + f3.y * vp[7];
            }
            float m = d;
            #pragma unroll
            for (int s = 16; s; s >>= 1) m = fmaxf(m, __shfl_xor_sync(0xffffffffu, m, s));
            const float e = __expf(d - m);
            float sum = e;
            #pragma unroll
            for (int s = 16; s; s >>= 1) sum += __shfl_xor_sync(0xffffffffu, sum, s);
            scoef[w * CN + l] = e / sum;
        }
        __syncthreads();

        // Phase B: thread owns co 4t..4t+3 (8B = half of granule t>>1), over 8 r
        {
            const int gB = swz(t >> 1);
            const int sub = (t & 1) * 8;
            #pragma unroll
            for (int q = 0; q < CH; q++) {
                const float cf = scoef[q * CN + myc];
                const uint2 v = *(const uint2*)((const char*)&ubuf[nb][q * COG + gB] + sub);
                const float2 f0 = __half22float2(*(const __half2*)&v.x);
                const float2 f1 = __half22float2(*(const __half2*)&v.y);
                acc.x += cf * f0.x; acc.y += cf * f0.y;
                acc.z += cf * f1.x; acc.w += cf * f1.y;
            }
        }
        __syncthreads();
    }

    g_part[((size_t)rt * BN + b) * CO4 + t] = acc;
}

// ===== squash: reduce partials, normalize over OUT. MODE 0: vsum=v; 1: +=; 2: out =====
template <int NP, int MODE, bool USE_P0>
__global__ void k_squash(const float scale, float* __restrict__ outp) {
    const int b = blockIdx.x;
    const int o = threadIdx.x;
    const int c = blockIdx.y * 8 + threadIdx.y;
    const float4* part = USE_P0 ? g_part0 : g_part;
    const size_t stride = (size_t)BN * CO;
    const size_t idx = (size_t)b * CO + c * ON + o;
    const float* pf = (const float*)part;

    float s = 0.f;
    #pragma unroll 16
    for (int p = 0; p < NP; p++) s += pf[p * stride + idx];
    s *= scale;

    float ss = s * s;
    #pragma unroll
    for (int sh = 16; sh; sh >>= 1) ss += __shfl_xor_sync(0xffffffffu, ss, sh);
    const float norm = sqrtf(ss);
    const float val = s * (ss / (1.f + ss)) / (norm + 1e-8f);

    if (MODE == 0) g_vsum[idx] = val;
    else if (MODE == 1) g_vsum[idx] += val;
    else outp[idx] = val;
}

__global__ void k_dummy() {}

extern "C" void kernel_launch(void* const* d_in, const int* in_sizes, int n_in,
                              void* d_out, int out_size) {
    const float* x = (const float*)d_in[0];  // [B, R, IN] f32
    const float* W = (const float*)d_in[1];  // [1, R, C, OUT, IN] f32
    float* out = (float*)d_out;              // [B, C, OUT] f32

    const int k1_smem = (32768 + 2 * 8192 + 2 * 1024) * 4;  // 200 KB
    cudaFuncSetAttribute(k1_uhat, cudaFuncAttributeMaxDynamicSharedMemorySize, k1_smem);

    // idx0-2: dummies so ncu's sampled launch (idx3) is k1_uhat
    k_dummy<<<1, 1>>>();
    k_dummy<<<1, 1>>>();
    k_dummy<<<1, 1>>>();
    // idx3: u_hat (fp16) + s0 partials
    k1_uhat<<<dim3(2, K1_NRT), 512, k1_smem>>>(x, W);
    // v0 -> vsum
    k_squash<K1_NRT, 0, true><<<dim3(BN, 4), dim3(32, 8)>>>(1.f / 32.f, nullptr);
    // coef = softmax(u.v0); s1 partials
    k_route<<<dim3(BN, RT_NRT), 256>>>();
    // v1; vsum += v1
    k_squash<RT_NRT, 1, false><<<dim3(BN, 4), dim3(32, 8)>>>(1.f, nullptr);
    // coef = softmax(u.(v0+v1)); s2 partials
    k_route<<<dim3(BN, RT_NRT), 256>>>();
    // v2 -> out
    k_squash<RT_NRT, 2, false><<<dim3(BN, 4), dim3(32, 8)>>>(1.f, out);
}